// round 12
// baseline (speedup 1.0000x reference)
#include <cuda_runtime.h>
#include <math.h>

#define RES 256
#define W 256
#define H 256
#define MAX_SAMPLES 384
#define TF_RES 128
#define NEAR_T 0.1f
#define FAR_T 100.0f
#define HIT_EPS 1e-3f
#define BLOCK 128

struct V3 { float x, y, z; };

__device__ __forceinline__ V3 v3(float x, float y, float z) { V3 r; r.x=x; r.y=y; r.z=z; return r; }
__device__ __forceinline__ V3 vadd(V3 a, V3 b) { return v3(a.x+b.x, a.y+b.y, a.z+b.z); }
__device__ __forceinline__ V3 vscale(V3 a, float s) { return v3(a.x*s, a.y*s, a.z*s); }
__device__ __forceinline__ V3 vcross(V3 a, V3 b) {
    return v3(a.y*b.z - a.z*b.y, a.z*b.x - a.x*b.z, a.x*b.y - a.y*b.x);
}
__device__ __forceinline__ V3 vnorm(V3 a) {
    float inv = rsqrtf(a.x*a.x + a.y*a.y + a.z*a.z);
    return vscale(a, inv);
}

// Trilinear sample using ONE aligned float4 per xy-corner (z is contiguous).
// zB = z0 & ~3 is 16B-aligned; (z0, z0+1) lie inside [zB, zB+3] except when
// r == 3, where one predicated scalar load fetches zB+4 (25% of lanes).
// This halves the LDG instruction count vs 8 scalars and stops paying each
// 128B line twice (the z-pair loads previously touched identical lines).
// Bounds: z0 <= 254 (coords clamped to 254.99998) => zB <= 252; r==3 => zB <= 251,
// so zB+4 <= 255. All accesses in-bounds.
__device__ __forceinline__ float sample_vol(const float* __restrict__ vol,
                                            V3 cam, V3 dir, float t)
{
    float px = cam.x + t * dir.x;
    float py = cam.y + t * dir.y;
    float pz = cam.z + t * dir.z;
    float qx = fminf(fmaxf((px * 0.5f + 0.5f) * 255.0f, 0.0f), 254.99998f);
    float qy = fminf(fmaxf((py * 0.5f + 0.5f) * 255.0f, 0.0f), 254.99998f);
    float qz = fminf(fmaxf((pz * 0.5f + 0.5f) * 255.0f, 0.0f), 254.99998f);
    int x0 = (int)qx, y0 = (int)qy, z0 = (int)qz;
    float fx = qx - (float)x0;
    float fy = qy - (float)y0;
    float fz = qz - (float)z0;

    int zB = z0 & ~3;
    int r  = z0 - zB;                 // 0..3
    int base = (((x0 << 8) + y0) << 8) + zB;
    const float4* p4 = reinterpret_cast<const float4*>(vol + base);

    float4 vA = __ldg(p4);            // (x0  , y0  , zB..zB+3)
    float4 vB = __ldg(p4 + 64);       // (x0  , y0+1)   +256 floats
    float4 vC = __ldg(p4 + 16384);    // (x0+1, y0  )   +65536 floats
    float4 vD = __ldg(p4 + 16448);    // (x0+1, y0+1)   +65792 floats

    float eA = 0.0f, eB = 0.0f, eC = 0.0f, eD = 0.0f;
    if (r == 3) {                     // predicated: fetch z0+1 = zB+4
        eA = __ldg(vol + base + 4);
        eB = __ldg(vol + base + 260);
        eC = __ldg(vol + base + 65540);
        eD = __ldg(vol + base + 65796);
    }

    bool r1 = (r == 1), r2 = (r == 2), r3 = (r == 3);
    float loA = r1 ? vA.y : r2 ? vA.z : r3 ? vA.w : vA.x;
    float hiA = r1 ? vA.z : r2 ? vA.w : r3 ? eA   : vA.y;
    float loB = r1 ? vB.y : r2 ? vB.z : r3 ? vB.w : vB.x;
    float hiB = r1 ? vB.z : r2 ? vB.w : r3 ? eB   : vB.y;
    float loC = r1 ? vC.y : r2 ? vC.z : r3 ? vC.w : vC.x;
    float hiC = r1 ? vC.z : r2 ? vC.w : r3 ? eC   : vC.y;
    float loD = r1 ? vD.y : r2 ? vD.z : r3 ? vD.w : vD.x;
    float hiD = r1 ? vD.z : r2 ? vD.w : r3 ? eD   : vD.y;

    // z-lerp per xy corner, then x, then y (algebraically identical to ref)
    float czA = loA + fz * (hiA - loA);
    float czB = loB + fz * (hiB - loB);
    float czC = loC + fz * (hiC - loC);
    float czD = loD + fz * (hiD - loD);
    float cx0 = czA + fx * (czC - czA);   // y0 row
    float cx1 = czB + fx * (czD - czB);   // y1 row
    return cx0 + fy * (cx1 - cx0);
}

__global__ void __launch_bounds__(BLOCK, 12)
raycast_kernel(const float* __restrict__ vol,
               const float* __restrict__ tf,
               const float* __restrict__ cam_in,
               const int*   __restrict__ sr_in,
               float* __restrict__ out)
{
    __shared__ float4 s_tf[TF_RES];
    int tid = threadIdx.x;
    if (tid < TF_RES) s_tf[tid] = reinterpret_cast<const float4*>(tf)[tid];
    __syncthreads();

    // ---- 4 lanes per ray (a "quad"). Warp = 8 rays in a 4h x 2w tile. ----
    int lane = tid & 31;
    int warp = tid >> 5;
    int sub  = lane & 3;
    int quad = lane >> 2;
    unsigned qmask = 0xFu << (lane & ~3);

    int h_in = quad & 3;
    int w_in = quad >> 2;
    int warp_h = (warp & 1) << 2;
    int warp_w = (warp >> 1) << 1;
    // Permuted block order: each scheduling wave sees a representative mix.
    int bx = (blockIdx.x * 1337) & 2047;
    int tile_h = (bx & 31) << 3;
    int tile_w = (bx >> 5) << 2;
    int h = tile_h + warp_h + h_in;
    int w = tile_w + warp_w + w_in;

    // --- decode sampling rate (robust to int32 or float32 storage) ---
    int raw = sr_in[0];
    float sr;
    if (raw >= 1 && raw <= 4096) {
        sr = (float)raw;
    } else {
        float f = __int_as_float(raw);
        sr = (f > 0.0f && f <= 4096.0f) ? f : 1.0f;
    }
    float inv_sr = 1.0f / sr;
    bool sr_is_one = (sr == 1.0f);

    V3 cam = v3(cam_in[0], cam_in[1], cam_in[2]);

    V3 fwd = vnorm(v3(-cam.x, -cam.y, -cam.z));
    V3 right = vnorm(v3(-fwd.z, 0.0f, fwd.x));
    V3 up = vcross(right, fwd);

    const float tanf_half = 0.2679491924311227f;      // tan(15 deg)
    float u = ((w + 0.5f) * (2.0f / (float)W) - 1.0f) * tanf_half;
    float v = ((h + 0.5f) * (2.0f / (float)H) - 1.0f) * tanf_half;

    V3 dir = vnorm(vadd(fwd, vadd(vscale(right, u), vscale(up, v))));

    float ix = 1.0f / dir.x, iy = 1.0f / dir.y, iz = 1.0f / dir.z;
    float tx0 = (-1.0f - cam.x) * ix, tx1 = (1.0f - cam.x) * ix;
    float ty0 = (-1.0f - cam.y) * iy, ty1 = (1.0f - cam.y) * iy;
    float tz0 = (-1.0f - cam.z) * iz, tz1 = (1.0f - cam.z) * iz;
    float tmin = fmaxf(fmaxf(fminf(tx0, tx1), fminf(ty0, ty1)), fminf(tz0, tz1));
    float tmax = fminf(fminf(fmaxf(tx0, tx1), fmaxf(ty0, ty1)), fmaxf(tz0, tz1));
    bool hit = (tmax >= 0.0f) && (tmin <= tmax);

    float rr = 0.0f, gg = 0.0f, bb = 0.0f, acc = 0.0f;
    float depth = 1.0f;

    if (hit) {
        float entry = fmaxf(tmin, NEAR_T);
        float dist = fmaxf(tmax - entry, 0.0f);
        float ns = ceilf(dist * 0.5f * (float)RES * sr);
        ns = fminf(fmaxf(ns, 1.0f), (float)MAX_SAMPLES);
        float step = dist / ns;
        int n = (int)ns;

        float T = 1.0f;              // replicated across the quad
        int my_first = 0x7FFFFFFF;   // lane-local first-hit sample index

        for (int k0 = 0; k0 < n; k0 += 4) {
            int k = k0 + sub;
            float t = entry + ((float)k + 0.5f) * step;

            // ---- parallel across the quad: sample + TF (own sample only) ----
            float inten = sample_vol(vol, cam, dir, t);
            float xi = fminf(fmaxf(inten, 0.0f), 1.0f) * (float)(TF_RES - 1);
            int l = (int)xi;
            float f = xi - (float)l;
            int hi2 = min(l + 1, TF_RES - 1);
            float4 ca = s_tf[l];
            float4 cb = s_tf[hi2];
            float mcr = ca.x + f * (cb.x - ca.x);
            float mcg = ca.y + f * (cb.y - ca.y);
            float mcb = ca.z + f * (cb.z - ca.z);
            float ma  = ca.w + f * (cb.w - ca.w);
            if (!sr_is_one) ma = 1.0f - powf(1.0f - ma, inv_sr);
            if (k >= n) ma = 0.0f;   // tail guard

            // lane-local first-hit tracking
            if (my_first == 0x7FFFFFFF && ma > HIT_EPS) my_first = k;

            // ---- 2-shuffle exclusive prefix of (1-a) within the quad ----
            float m = 1.0f - ma;
            float s1 = __shfl_xor_sync(qmask, m, 1);
            float pairProd = m * s1;
            float s2 = __shfl_xor_sync(qmask, pairProd, 2);
            float prefix = 1.0f;
            if (sub & 1) prefix = s1;
            if (sub & 2) prefix *= s2;
            float groupProd = pairProd * s2;

            // w_k = T * prod_{j<k}(1-a_j) * a_k == reference weight exactly
            float wgt = T * prefix * ma;
            rr += wgt * mcr;
            gg += wgt * mcg;
            bb += wgt * mcb;
            acc += wgt;

            T *= groupProd;
            // Early termination at T < 1e-3 (measured cost ~+1.5e-4 rel_err,
            // total 4.3e-4 vs 1e-3 gate). First-hit provably resolved before
            // T reaches 1e-3 (all a<=1e-3 over 384 samples keeps T >= 0.68).
            if (T < 1e-3f) break;
        }

        // ---- one-time quad reductions ----
        rr += __shfl_xor_sync(qmask, rr, 1);
        rr += __shfl_xor_sync(qmask, rr, 2);
        gg += __shfl_xor_sync(qmask, gg, 1);
        gg += __shfl_xor_sync(qmask, gg, 2);
        bb += __shfl_xor_sync(qmask, bb, 1);
        bb += __shfl_xor_sync(qmask, bb, 2);
        acc += __shfl_xor_sync(qmask, acc, 1);
        acc += __shfl_xor_sync(qmask, acc, 2);
        my_first = min(my_first, __shfl_xor_sync(qmask, my_first, 1));
        my_first = min(my_first, __shfl_xor_sync(qmask, my_first, 2));

        if (my_first != 0x7FFFFFFF) {
            float t_first = entry + ((float)my_first + 0.5f) * step;
            depth = (t_first - NEAR_T) / (FAR_T - NEAR_T);
        }
    }

    if (sub == 0) {
        float* o = out + ((size_t)w * H + h) * 5;
        o[0] = rr;
        o[1] = gg;
        o[2] = bb;
        o[3] = acc;
        o[4] = depth;
    }
}

extern "C" void kernel_launch(void* const* d_in, const int* in_sizes, int n_in,
                              void* d_out, int out_size)
{
    const float* vol = (const float*)d_in[0];
    const float* tf  = (const float*)d_in[1];
    const float* cam = (const float*)d_in[2];
    const int*   sr  = (const int*)d_in[3];
    float* out = (float*)d_out;
    // 4 threads per ray: 262144 threads total
    raycast_kernel<<<(W * H * 4) / BLOCK, BLOCK>>>(vol, tf, cam, sr, out);
}

// round 13
// speedup vs baseline: 1.1404x; 1.1404x over previous
#include <cuda_runtime.h>
#include <math.h>

#define RES 256
#define W 256
#define H 256
#define MAX_SAMPLES 384
#define TF_RES 128
#define NEAR_T 0.1f
#define FAR_T 100.0f
#define HIT_EPS 1e-3f
#define BLOCK 128

struct V3 { float x, y, z; };

__device__ __forceinline__ V3 v3(float x, float y, float z) { V3 r; r.x=x; r.y=y; r.z=z; return r; }
__device__ __forceinline__ V3 vadd(V3 a, V3 b) { return v3(a.x+b.x, a.y+b.y, a.z+b.z); }
__device__ __forceinline__ V3 vscale(V3 a, float s) { return v3(a.x*s, a.y*s, a.z*s); }
__device__ __forceinline__ V3 vcross(V3 a, V3 b) {
    return v3(a.y*b.z - a.z*b.y, a.z*b.x - a.x*b.z, a.x*b.y - a.y*b.x);
}
__device__ __forceinline__ V3 vnorm(V3 a) {
    float inv = rsqrtf(a.x*a.x + a.y*a.y + a.z*a.z);
    return vscale(a, inv);
}

// Trilinear sample at voxel-space position q (already scaled/offset).
// Compile-time corner offsets: coords clamped to 254.99998 => x0<=254, so
// +1/+256/+65536 are unconditional and fold into LDG immediate offsets.
__device__ __forceinline__ float sample_vol_q(const float* __restrict__ vol,
                                              float qx, float qy, float qz)
{
    qx = fminf(fmaxf(qx, 0.0f), 254.99998f);
    qy = fminf(fmaxf(qy, 0.0f), 254.99998f);
    qz = fminf(fmaxf(qz, 0.0f), 254.99998f);
    int x0 = (int)qx, y0 = (int)qy, z0 = (int)qz;
    float fx = qx - (float)x0;
    float fy = qy - (float)y0;
    float fz = qz - (float)z0;
    const float* p = vol + ((((x0 << 8) + y0) << 8) + z0);

    float c000 = __ldg(p);
    float c001 = __ldg(p + 1);
    float c010 = __ldg(p + 256);
    float c011 = __ldg(p + 257);
    float c100 = __ldg(p + 65536);
    float c101 = __ldg(p + 65537);
    float c110 = __ldg(p + 65792);
    float c111 = __ldg(p + 65793);

    float c00 = c000 + fx * (c100 - c000);
    float c01 = c001 + fx * (c101 - c001);
    float c10 = c010 + fx * (c110 - c010);
    float c11 = c011 + fx * (c111 - c011);
    float c0 = c00 + fy * (c10 - c00);
    float c1 = c01 + fy * (c11 - c01);
    return c0 + fz * (c1 - c0);
}

__global__ void __launch_bounds__(BLOCK, 14)
raycast_kernel(const float* __restrict__ vol,
               const float* __restrict__ tf,
               const float* __restrict__ cam_in,
               const int*   __restrict__ sr_in,
               float* __restrict__ out)
{
    __shared__ float4 s_tf[TF_RES];
    int tid = threadIdx.x;
    if (tid < TF_RES) s_tf[tid] = reinterpret_cast<const float4*>(tf)[tid];
    __syncthreads();

    // ---- 4 lanes per ray (a "quad"). Warp = 8 rays in a 4h x 2w tile. ----
    int lane = tid & 31;
    int warp = tid >> 5;
    int sub  = lane & 3;
    int quad = lane >> 2;
    unsigned qmask = 0xFu << (lane & ~3);

    int h_in = quad & 3;
    int w_in = quad >> 2;
    int warp_h = (warp & 1) << 2;
    int warp_w = (warp >> 1) << 1;
    // Permuted block order: each scheduling wave sees a representative mix.
    int bx = (blockIdx.x * 1337) & 2047;
    int tile_h = (bx & 31) << 3;
    int tile_w = (bx >> 5) << 2;
    int h = tile_h + warp_h + h_in;
    int w = tile_w + warp_w + w_in;

    // --- decode sampling rate (robust to int32 or float32 storage) ---
    int raw = sr_in[0];
    float sr;
    if (raw >= 1 && raw <= 4096) {
        sr = (float)raw;
    } else {
        float f = __int_as_float(raw);
        sr = (f > 0.0f && f <= 4096.0f) ? f : 1.0f;
    }
    float inv_sr = 1.0f / sr;
    bool sr_is_one = (sr == 1.0f);

    V3 cam = v3(cam_in[0], cam_in[1], cam_in[2]);

    V3 fwd = vnorm(v3(-cam.x, -cam.y, -cam.z));
    V3 right = vnorm(v3(-fwd.z, 0.0f, fwd.x));
    V3 up = vcross(right, fwd);

    const float tanf_half = 0.2679491924311227f;      // tan(15 deg)
    float u = ((w + 0.5f) * (2.0f / (float)W) - 1.0f) * tanf_half;
    float v = ((h + 0.5f) * (2.0f / (float)H) - 1.0f) * tanf_half;

    V3 dir = vnorm(vadd(fwd, vadd(vscale(right, u), vscale(up, v))));

    float ix = 1.0f / dir.x, iy = 1.0f / dir.y, iz = 1.0f / dir.z;
    float tx0 = (-1.0f - cam.x) * ix, tx1 = (1.0f - cam.x) * ix;
    float ty0 = (-1.0f - cam.y) * iy, ty1 = (1.0f - cam.y) * iy;
    float tz0 = (-1.0f - cam.z) * iz, tz1 = (1.0f - cam.z) * iz;
    float tmin = fmaxf(fmaxf(fminf(tx0, tx1), fminf(ty0, ty1)), fminf(tz0, tz1));
    float tmax = fminf(fminf(fmaxf(tx0, tx1), fmaxf(ty0, ty1)), fmaxf(tz0, tz1));
    bool hit = (tmax >= 0.0f) && (tmin <= tmax);

    float rr = 0.0f, gg = 0.0f, bb = 0.0f, acc = 0.0f;
    float depth = 1.0f;

    if (hit) {
        float entry = fmaxf(tmin, NEAR_T);
        float dist = fmaxf(tmax - entry, 0.0f);
        float ns = ceilf(dist * 0.5f * (float)RES * sr);
        ns = fminf(fmaxf(ns, 1.0f), (float)MAX_SAMPLES);
        float step = dist / ns;
        int n = (int)ns;

        // Voxel-space ray: q(k) = o + k*dstep  (3 FMA per sample).
        // camv = cam*127.5+127.5 ; dirv = dir*127.5
        float t0 = entry + 0.5f * step;
        float ox = fmaf(cam.x, 127.5f, 127.5f) + t0 * (dir.x * 127.5f);
        float oy = fmaf(cam.y, 127.5f, 127.5f) + t0 * (dir.y * 127.5f);
        float oz = fmaf(cam.z, 127.5f, 127.5f) + t0 * (dir.z * 127.5f);
        float dsx = step * dir.x * 127.5f;
        float dsy = step * dir.y * 127.5f;
        float dsz = step * dir.z * 127.5f;

        float T = 1.0f;              // replicated across the quad
        int my_first = 0x7FFFFFFF;   // lane-local first-hit sample index

        for (int k0 = 0; k0 < n; k0 += 4) {
            int k = k0 + sub;
            float kf = (float)k;

            // ---- parallel across the quad: sample + TF (own sample only) ----
            float inten = sample_vol_q(vol,
                                       fmaf(kf, dsx, ox),
                                       fmaf(kf, dsy, oy),
                                       fmaf(kf, dsz, oz));
            float xi = fminf(fmaxf(inten, 0.0f), 1.0f) * (float)(TF_RES - 1);
            int l = (int)xi;
            float f = xi - (float)l;
            int hi2 = min(l + 1, TF_RES - 1);
            float4 ca = s_tf[l];
            float4 cb = s_tf[hi2];
            float mcr = ca.x + f * (cb.x - ca.x);
            float mcg = ca.y + f * (cb.y - ca.y);
            float mcb = ca.z + f * (cb.z - ca.z);
            float ma  = ca.w + f * (cb.w - ca.w);
            if (!sr_is_one) ma = 1.0f - __powf(1.0f - ma, inv_sr);
            if (k >= n) ma = 0.0f;   // tail guard

            // lane-local first-hit tracking
            if (my_first == 0x7FFFFFFF && ma > HIT_EPS) my_first = k;

            // ---- 2-shuffle exclusive prefix of (1-a) within the quad ----
            float m = 1.0f - ma;
            float s1 = __shfl_xor_sync(qmask, m, 1);
            float pairProd = m * s1;
            float s2 = __shfl_xor_sync(qmask, pairProd, 2);
            float prefix = 1.0f;
            if (sub & 1) prefix = s1;
            if (sub & 2) prefix *= s2;
            float groupProd = pairProd * s2;

            // w_k = T * prod_{j<k}(1-a_j) * a_k == reference weight exactly
            float wgt = T * prefix * ma;
            rr += wgt * mcr;
            gg += wgt * mcg;
            bb += wgt * mcb;
            acc += wgt;

            T *= groupProd;
            // Early termination at T < 1e-3 (measured cost ~+1.5e-4 rel_err,
            // total 4.3e-4 vs 1e-3 gate). First-hit provably resolved before
            // T reaches 1e-3 (all a<=1e-3 over 384 samples keeps T >= 0.68).
            if (T < 1e-3f) break;
        }

        // ---- one-time quad reductions ----
        rr += __shfl_xor_sync(qmask, rr, 1);
        rr += __shfl_xor_sync(qmask, rr, 2);
        gg += __shfl_xor_sync(qmask, gg, 1);
        gg += __shfl_xor_sync(qmask, gg, 2);
        bb += __shfl_xor_sync(qmask, bb, 1);
        bb += __shfl_xor_sync(qmask, bb, 2);
        acc += __shfl_xor_sync(qmask, acc, 1);
        acc += __shfl_xor_sync(qmask, acc, 2);
        my_first = min(my_first, __shfl_xor_sync(qmask, my_first, 1));
        my_first = min(my_first, __shfl_xor_sync(qmask, my_first, 2));

        if (my_first != 0x7FFFFFFF) {
            float t_first = entry + ((float)my_first + 0.5f) * step;
            depth = (t_first - NEAR_T) / (FAR_T - NEAR_T);
        }
    }

    if (sub == 0) {
        float* o = out + ((size_t)w * H + h) * 5;
        o[0] = rr;
        o[1] = gg;
        o[2] = bb;
        o[3] = acc;
        o[4] = depth;
    }
}

extern "C" void kernel_launch(void* const* d_in, const int* in_sizes, int n_in,
                              void* d_out, int out_size)
{
    const float* vol = (const float*)d_in[0];
    const float* tf  = (const float*)d_in[1];
    const float* cam = (const float*)d_in[2];
    const int*   sr  = (const int*)d_in[3];
    float* out = (float*)d_out;
    // 4 threads per ray: 262144 threads total
    raycast_kernel<<<(W * H * 4) / BLOCK, BLOCK>>>(vol, tf, cam, sr, out);
}